// round 5
// baseline (speedup 1.0000x reference)
#include <cuda_runtime.h>
#include <cuda_bf16.h>
#include <math.h>

// ---------------- Problem constants ----------------
#define B_    2
#define S_    2048
#define EMB_  2048
#define NH_   32
#define NKV_  8
#define GS_   4
#define HD_   64
#define WIN_  128
#define MROWS (B_*S_)          // 4096

// ---------------- Scratch (device globals; no allocation) ----------------
__device__ float g_Q[(size_t)MROWS * NH_ * HD_];    // [4096, 2048]
__device__ float g_K[(size_t)MROWS * NKV_ * HD_];   // [4096, 512]
__device__ float g_V[(size_t)MROWS * NKV_ * HD_];   // [4096, 512]
__device__ float g_ctx[(size_t)MROWS * NH_ * HD_];  // [4096, 2048]

// ======================================================================
// SGEMM: C[M,N] = A[M,K] @ W[N,K]^T + bias[N]
// BM=BN=128, BK=8, 256 threads, 8x8 per thread, double-buffered smem.
// asel: 0 -> A = Aext, 1 -> A = g_ctx
// dsel: 0 -> C = Cext, 1 -> g_Q, 2 -> g_K, 3 -> g_V
// All dims are multiples of tile sizes for this problem (no guards).
// ======================================================================
#define BM 128
#define BN 128
#define BK 8

__global__ __launch_bounds__(256, 2)
void gemm128(const float* __restrict__ Aext, const float* __restrict__ W,
             const float* __restrict__ bias, float* __restrict__ Cext,
             int asel, int dsel, int M, int N, int K)
{
    const float* A = (asel == 1) ? (const float*)g_ctx : Aext;
    float* C = (dsel == 1) ? g_Q : (dsel == 2) ? g_K : (dsel == 3) ? g_V : Cext;

    __shared__ float As[2][BK][BM];
    __shared__ float Bs[2][BK][BN];

    const int tid = threadIdx.x;
    const int m0 = blockIdx.y * BM;
    const int n0 = blockIdx.x * BN;

    const int lrow = tid >> 1;          // 0..127
    const int lcol = (tid & 1) * 4;     // 0 or 4

    const float* Aptr = A + (size_t)(m0 + lrow) * K + lcol;
    const float* Wptr = W + (size_t)(n0 + lrow) * K + lcol;

    const int tx = tid & 15;
    const int ty = tid >> 4;

    float acc[8][8];
    #pragma unroll
    for (int i = 0; i < 8; i++)
        #pragma unroll
        for (int j = 0; j < 8; j++) acc[i][j] = 0.0f;

    // preload tile 0
    {
        float4 a  = *(const float4*)Aptr;
        float4 wv = *(const float4*)Wptr;
        As[0][lcol + 0][lrow] = a.x;  As[0][lcol + 1][lrow] = a.y;
        As[0][lcol + 2][lrow] = a.z;  As[0][lcol + 3][lrow] = a.w;
        Bs[0][lcol + 0][lrow] = wv.x; Bs[0][lcol + 1][lrow] = wv.y;
        Bs[0][lcol + 2][lrow] = wv.z; Bs[0][lcol + 3][lrow] = wv.w;
    }
    __syncthreads();

    const int nt = K >> 3;
    for (int t = 0; t < nt; t++) {
        const int cur = t & 1;
        float4 na, nw;
        const bool more = (t + 1 < nt);
        if (more) {
            na = *(const float4*)(Aptr + (size_t)(t + 1) * BK);
            nw = *(const float4*)(Wptr + (size_t)(t + 1) * BK);
        }
        #pragma unroll
        for (int k = 0; k < BK; k++) {
            float4 a0 = *(const float4*)&As[cur][k][ty * 4];
            float4 a1 = *(const float4*)&As[cur][k][64 + ty * 4];
            float4 b0 = *(const float4*)&Bs[cur][k][tx * 4];
            float4 b1 = *(const float4*)&Bs[cur][k][64 + tx * 4];
            float ra[8] = {a0.x, a0.y, a0.z, a0.w, a1.x, a1.y, a1.z, a1.w};
            float rb[8] = {b0.x, b0.y, b0.z, b0.w, b1.x, b1.y, b1.z, b1.w};
            #pragma unroll
            for (int i = 0; i < 8; i++)
                #pragma unroll
                for (int j = 0; j < 8; j++)
                    acc[i][j] += ra[i] * rb[j];
        }
        if (more) {
            const int nxt = cur ^ 1;
            As[nxt][lcol + 0][lrow] = na.x; As[nxt][lcol + 1][lrow] = na.y;
            As[nxt][lcol + 2][lrow] = na.z; As[nxt][lcol + 3][lrow] = na.w;
            Bs[nxt][lcol + 0][lrow] = nw.x; Bs[nxt][lcol + 1][lrow] = nw.y;
            Bs[nxt][lcol + 2][lrow] = nw.z; Bs[nxt][lcol + 3][lrow] = nw.w;
            __syncthreads();
        }
    }

    // epilogue: + bias, vectorized stores
    float bcol[8];
    #pragma unroll
    for (int j = 0; j < 4; j++) bcol[j] = bias[n0 + tx * 4 + j];
    #pragma unroll
    for (int j = 4; j < 8; j++) bcol[j] = bias[n0 + 64 + tx * 4 + (j - 4)];

    #pragma unroll
    for (int i = 0; i < 8; i++) {
        const int row = m0 + ((i < 4) ? (ty * 4 + i) : (64 + ty * 4 + (i - 4)));
        float* crow = C + (size_t)row * N + n0;
        float4 v0, v1;
        v0.x = acc[i][0] + bcol[0]; v0.y = acc[i][1] + bcol[1];
        v0.z = acc[i][2] + bcol[2]; v0.w = acc[i][3] + bcol[3];
        v1.x = acc[i][4] + bcol[4]; v1.y = acc[i][5] + bcol[5];
        v1.z = acc[i][6] + bcol[6]; v1.w = acc[i][7] + bcol[7];
        *(float4*)&crow[tx * 4]      = v0;
        *(float4*)&crow[64 + tx * 4] = v1;
    }
}

// ======================================================================
// RoPE (YaRN), applied in place to g_Q and g_K.
// One thread per rotation pair. Totals: 4096 rows * (32+8) heads * 32 pairs.
// ======================================================================
__global__ __launch_bounds__(256)
void rope_kernel(const int* __restrict__ pos_ids)
{
    const int gid = blockIdx.x * blockDim.x + threadIdx.x;
    const int i   = gid & 31;          // pair index 0..31
    const int rh  = gid >> 5;          // row*40 + head
    const int hr  = rh % (NH_ + NKV_); // 0..39
    const int row = rh / (NH_ + NKV_); // 0..4095

    const int p = pos_ids[row];

    float* ptr;
    if (hr < NH_) ptr = g_Q + ((size_t)row * NH_ + hr) * HD_;
    else          ptr = g_K + ((size_t)row * NKV_ + (hr - NH_)) * HD_;

    // freqs = 1 / 10000^(2i/64); YaRN blend
    const float expo = (float)(2 * i) * (1.0f / 64.0f);
    const float freq = 1.0f / powf(10000.0f, expo);
    const float wl   = 6.2831853071795864769f / freq;
    float tt = (wl - 32.0f) / 992.0f;          // (wl - low)/(high - low)
    tt = fminf(fmaxf(tt, 0.0f), 1.0f);
    const float eff  = freq * (1.0f - tt) + (freq * 0.25f) * tt;
    const float ang  = ((float)p * eff) * 1.1386294361119891f;  // * conc

    float sv, cv;
    sincosf(ang, &sv, &cv);

    const float x1 = ptr[i];
    const float x2 = ptr[i + 32];
    ptr[i]      = x1 * cv - x2 * sv;
    ptr[i + 32] = x2 * cv + x1 * sv;
}

// ======================================================================
// Sliding-window GQA attention with sink.
// Grid: (S/128, NKV, B). 256 threads. K/V window (255 keys) in dyn smem.
// Warp per query row; 4 score chunks of 32 keys per lane; sink in denom.
// ======================================================================
#define KWIN 255
#define PITCH 65
#define ATT_SMEM ((2 * KWIN * PITCH + 8 * 64) * (int)sizeof(float))

__global__ __launch_bounds__(256, 1)
void attn_kernel(const float* __restrict__ sinks)
{
    extern __shared__ float sm[];
    float* Ks = sm;                       // [255][65]
    float* Vs = sm + KWIN * PITCH;        // [255][65]
    float* Qw = Vs + KWIN * PITCH;        // [8][64]

    const int tid  = threadIdx.x;
    const int w    = tid >> 5;
    const int lane = tid & 31;
    const int qt   = blockIdx.x;
    const int kvh  = blockIdx.y;
    const int b    = blockIdx.z;
    const int q0   = qt * 128;

    // Stage K/V window: keys t in [q0-127, q0+127]; zero-fill t<0.
    for (int idx = tid; idx < KWIN * HD_; idx += 256) {
        const int kt = idx >> 6;
        const int d  = idx & 63;
        const int t  = q0 - 127 + kt;
        float kv = 0.0f, vv = 0.0f;
        if (t >= 0) {
            const size_t base = ((size_t)(b * S_ + t) * NKV_ + kvh) * HD_ + d;
            kv = g_K[base];
            vv = g_V[base];
        }
        Ks[kt * PITCH + d] = kv;
        Vs[kt * PITCH + d] = vv;
    }
    __syncthreads();

    for (int g = 0; g < GS_; g++) {
        const int h = kvh * GS_ + g;
        const float sinkv = sinks[h];

        for (int r = w; r < 128; r += 8) {
            const int s = q0 + r;
            const float* Qrow = g_Q + ((size_t)(b * S_ + s) * NH_ + h) * HD_;
            __syncwarp();
            Qw[w * 64 + lane]      = Qrow[lane];
            Qw[w * 64 + lane + 32] = Qrow[lane + 32];
            __syncwarp();

            // 128 keys = 4 chunks of 32 (lane-per-key); kt = r + c*32 + lane
            float sc0 = 0.f, sc1 = 0.f, sc2 = 0.f, sc3 = 0.f;
            const float* kp = Ks + (r + lane) * PITCH;
            const float* qp = Qw + w * 64;
            #pragma unroll 8
            for (int d = 0; d < 64; d++) {
                const float qd = qp[d];
                sc0 += qd * kp[d];
                sc1 += qd * kp[32 * PITCH + d];
                sc2 += qd * kp[64 * PITCH + d];
                sc3 += qd * kp[96 * PITCH + d];
            }
            const float NEG = -1e30f;
            const int tb = q0 - 127 + r + lane;  // t of chunk 0's key
            sc0 = (tb      >= 0) ? sc0 * 0.125f : NEG;
            sc1 = (tb + 32 >= 0) ? sc1 * 0.125f : NEG;
            sc2 = (tb + 64 >= 0) ? sc2 * 0.125f : NEG;
            sc3 = (tb + 96 >= 0) ? sc3 * 0.125f : NEG;

            // softmax over [sink, scores]
            float m = fmaxf(fmaxf(sc0, sc1), fmaxf(sc2, sc3));
            #pragma unroll
            for (int o = 16; o; o >>= 1)
                m = fmaxf(m, __shfl_xor_sync(0xffffffffu, m, o));
            m = fmaxf(m, sinkv);

            const float e0 = __expf(sc0 - m), e1 = __expf(sc1 - m);
            const float e2 = __expf(sc2 - m), e3 = __expf(sc3 - m);
            float sum = e0 + e1 + e2 + e3;
            #pragma unroll
            for (int o = 16; o; o >>= 1)
                sum += __shfl_xor_sync(0xffffffffu, sum, o);
            sum += __expf(sinkv - m);
            const float inv = 1.0f / sum;
            float p[4] = {e0 * inv, e1 * inv, e2 * inv, e3 * inv};

            // ctx[d] = sum_t p_t * V[t][d]; lane covers d=lane, lane+32
            float o0 = 0.f, o1 = 0.f;
            #pragma unroll
            for (int c = 0; c < 4; c++) {
                const float* vp = Vs + (r + c * 32) * PITCH;
                #pragma unroll 8
                for (int l2 = 0; l2 < 32; l2++) {
                    const float pt = __shfl_sync(0xffffffffu, p[c], l2);
                    o0 += pt * vp[l2 * PITCH + lane];
                    o1 += pt * vp[l2 * PITCH + lane + 32];
                }
            }
            float* orow = g_ctx + (size_t)(b * S_ + s) * (NH_ * HD_) + h * HD_;
            orow[lane]      = o0;
            orow[lane + 32] = o1;
        }
    }
}

// ======================================================================
// Launch
// ======================================================================
extern "C" void kernel_launch(void* const* d_in, const int* in_sizes, int n_in,
                              void* d_out, int out_size)
{
    const float* x     = (const float*)d_in[0];
    const float* Wq    = (const float*)d_in[1];
    const float* bq    = (const float*)d_in[2];
    const float* Wk    = (const float*)d_in[3];
    const float* bk    = (const float*)d_in[4];
    const float* Wv    = (const float*)d_in[5];
    const float* bv    = (const float*)d_in[6];
    const float* Wo    = (const float*)d_in[7];
    const float* bo    = (const float*)d_in[8];
    const float* sinks = (const float*)d_in[9];
    const int*   pos   = (const int*)d_in[10];
    float* out = (float*)d_out;

    cudaFuncSetAttribute(attn_kernel,
                         cudaFuncAttributeMaxDynamicSharedMemorySize, ATT_SMEM);

    dim3 blk(256);
    // QKV projections
    gemm128<<<dim3(NH_ * HD_ / BN,  MROWS / BM), blk>>>(x, Wq, bq, nullptr, 0, 1,
                                                        MROWS, NH_ * HD_, EMB_);
    gemm128<<<dim3(NKV_ * HD_ / BN, MROWS / BM), blk>>>(x, Wk, bk, nullptr, 0, 2,
                                                        MROWS, NKV_ * HD_, EMB_);
    gemm128<<<dim3(NKV_ * HD_ / BN, MROWS / BM), blk>>>(x, Wv, bv, nullptr, 0, 3,
                                                        MROWS, NKV_ * HD_, EMB_);
    // RoPE on Q and K
    {
        const int total = MROWS * (NH_ + NKV_) * 32;
        rope_kernel<<<total / 256, 256>>>(pos);
    }
    // Attention -> g_ctx
    attn_kernel<<<dim3(S_ / 128, NKV_, B_), 256, ATT_SMEM>>>(sinks);
    // Output projection
    gemm128<<<dim3(EMB_ / BN, MROWS / BM), blk>>>(nullptr, Wo, bo, out, 1, 0,
                                                  MROWS, EMB_, EMB_);
}

// round 6
// speedup vs baseline: 1.6601x; 1.6601x over previous
#include <cuda_runtime.h>
#include <cuda_bf16.h>
#include <math.h>

// ---------------- Problem constants ----------------
#define B_    2
#define S_    2048
#define EMB_  2048
#define NH_   32
#define NKV_  8
#define GS_   4
#define HD_   64
#define WIN_  128
#define MROWS (B_*S_)          // 4096

// ---------------- fp32 scratch ----------------
__device__ float g_Q[(size_t)MROWS * NH_ * HD_];    // [4096, 2048]
__device__ float g_K[(size_t)MROWS * NKV_ * HD_];   // [4096, 512]
__device__ float g_V[(size_t)MROWS * NKV_ * HD_];   // [4096, 512]
__device__ float g_ctx[(size_t)MROWS * NH_ * HD_];  // [4096, 2048]

// ---------------- bf16 hi/lo split scratch ----------------
__device__ __nv_bfloat16 gxh[(size_t)MROWS * EMB_];
__device__ __nv_bfloat16 gxl[(size_t)MROWS * EMB_];
__device__ __nv_bfloat16 gch[(size_t)MROWS * EMB_];
__device__ __nv_bfloat16 gcl[(size_t)MROWS * EMB_];
__device__ __nv_bfloat16 gwqh[(size_t)NH_ * HD_ * EMB_];
__device__ __nv_bfloat16 gwql[(size_t)NH_ * HD_ * EMB_];
__device__ __nv_bfloat16 gwkh[(size_t)NKV_ * HD_ * EMB_];
__device__ __nv_bfloat16 gwkl[(size_t)NKV_ * HD_ * EMB_];
__device__ __nv_bfloat16 gwvh[(size_t)NKV_ * HD_ * EMB_];
__device__ __nv_bfloat16 gwvl[(size_t)NKV_ * HD_ * EMB_];
__device__ __nv_bfloat16 gwoh[(size_t)EMB_ * NH_ * HD_];
__device__ __nv_bfloat16 gwol[(size_t)EMB_ * NH_ * HD_];

// ======================================================================
// fp32 -> bf16 hi/lo split. 4 elems/thread.
// ssel: 0 = src_ext, 1 = g_ctx
// dsel: 0=x, 1=Wq, 2=Wk, 3=Wv, 4=Wo, 5=ctx
// ======================================================================
__global__ __launch_bounds__(256)
void convert_kernel(const float* __restrict__ src_ext, int ssel, int dsel)
{
    const int i = (blockIdx.x * 256 + threadIdx.x) * 4;
    const float* s = ssel ? (const float*)g_ctx : src_ext;
    __nv_bfloat16 *dh, *dl;
    switch (dsel) {
        case 0: dh = gxh;  dl = gxl;  break;
        case 1: dh = gwqh; dl = gwql; break;
        case 2: dh = gwkh; dl = gwkl; break;
        case 3: dh = gwvh; dl = gwvl; break;
        case 4: dh = gwoh; dl = gwol; break;
        default: dh = gch; dl = gcl;  break;
    }
    float4 v = *(const float4*)(s + i);
    float vv[4] = {v.x, v.y, v.z, v.w};
    #pragma unroll
    for (int j = 0; j < 4; j++) {
        __nv_bfloat16 h = __float2bfloat16(vv[j]);
        float r = vv[j] - __bfloat162float(h);
        dh[i + j] = h;
        dl[i + j] = __float2bfloat16(r);
    }
}

// ======================================================================
// bf16 split-GEMM: C[M,N] = (Ah+Al)[M,K] @ (Bh+Bl)[N,K]^T + bias
//   = Ah·Bh + Ah·Bl + Al·Bh   (fp32 accum, lo*lo dropped)
// 128x128x32 tiles, 256 threads (8 warps, 4x2), warp tile 32x64.
// mma.sync m16n8k16 bf16; cp.async double-buffered smem, pitch 40 (80B).
// ======================================================================
#define PIT 40
#define STG (128 * PIT)   // 5120 elems per array per stage

__device__ __forceinline__ void cp16(void* sp, const void* gp)
{
    unsigned sa = (unsigned)__cvta_generic_to_shared(sp);
    asm volatile("cp.async.cg.shared.global [%0], [%1], 16;\n" :: "r"(sa), "l"(gp));
}
__device__ __forceinline__ void ldsm4(unsigned& r0, unsigned& r1,
                                      unsigned& r2, unsigned& r3, const void* p)
{
    unsigned a = (unsigned)__cvta_generic_to_shared(p);
    asm volatile("ldmatrix.sync.aligned.m8n8.x4.shared.b16 {%0,%1,%2,%3}, [%4];\n"
                 : "=r"(r0), "=r"(r1), "=r"(r2), "=r"(r3) : "r"(a));
}
__device__ __forceinline__ void mma16816(float* d, const unsigned* a,
                                         unsigned b0, unsigned b1)
{
    asm volatile("mma.sync.aligned.m16n8k16.row.col.f32.bf16.bf16.f32 "
                 "{%0,%1,%2,%3}, {%4,%5,%6,%7}, {%8,%9}, {%0,%1,%2,%3};\n"
                 : "+f"(d[0]), "+f"(d[1]), "+f"(d[2]), "+f"(d[3])
                 : "r"(a[0]), "r"(a[1]), "r"(a[2]), "r"(a[3]), "r"(b0), "r"(b1));
}

__global__ __launch_bounds__(256, 2)
void gemm_bf16(int asel, int bsel, int dsel, const float* __restrict__ bias,
               float* __restrict__ Cext, int M, int N, int K)
{
    const __nv_bfloat16 *Agh, *Agl, *Bgh, *Bgl;
    if (asel == 0) { Agh = gxh; Agl = gxl; } else { Agh = gch; Agl = gcl; }
    if (bsel == 0)      { Bgh = gwqh; Bgl = gwql; }
    else if (bsel == 1) { Bgh = gwkh; Bgl = gwkl; }
    else if (bsel == 2) { Bgh = gwvh; Bgl = gwvl; }
    else                { Bgh = gwoh; Bgl = gwol; }
    float* C = (dsel == 1) ? g_Q : (dsel == 2) ? g_K : (dsel == 3) ? g_V : Cext;

    extern __shared__ __nv_bfloat16 sm[];
    const int tid  = threadIdx.x;
    const int lane = tid & 31, wid = tid >> 5;
    const int wm = wid & 3, wn = wid >> 2;
    const int m0 = blockIdx.y * 128, n0 = blockIdx.x * 128;
    const int m0w = wm * 32, n0w = wn * 64;

    // cp.async mapping: thread -> (row, 16-elem half), two 16B chunks each
    const int lr = tid >> 1;
    const int lc = (tid & 1) * 16;
    const size_t gAo = (size_t)(m0 + lr) * K + lc;
    const size_t gBo = (size_t)(n0 + lr) * K + lc;
    const int sOff = lr * PIT + lc;

    // ldmatrix per-lane offsets
    const int g8 = lane >> 3, r8 = lane & 7;
    const int aRow  = ((g8 & 1) << 3) + r8;
    const int aColK = (g8 >> 1) << 3;
    const int bRow  = ((g8 >> 1) << 3) + r8;
    const int bColK = (g8 & 1) << 3;
    int aoff[2], boff[4];
    #pragma unroll
    for (int mt = 0; mt < 2; mt++)
        aoff[mt] = (m0w + mt * 16 + aRow) * PIT + aColK;
    #pragma unroll
    for (int gn = 0; gn < 4; gn++)
        boff[gn] = (n0w + gn * 16 + bRow) * PIT + bColK;

    float acc[2][8][4];
    #pragma unroll
    for (int i = 0; i < 2; i++)
        #pragma unroll
        for (int j = 0; j < 8; j++)
            #pragma unroll
            for (int q = 0; q < 4; q++) acc[i][j][q] = 0.0f;

    // prefetch stage 0
    {
        __nv_bfloat16* b0p = sm;
        cp16(b0p + sOff,               Agh + gAo);
        cp16(b0p + sOff + 8,           Agh + gAo + 8);
        cp16(b0p + STG + sOff,         Agl + gAo);
        cp16(b0p + STG + sOff + 8,     Agl + gAo + 8);
        cp16(b0p + 2 * STG + sOff,     Bgh + gBo);
        cp16(b0p + 2 * STG + sOff + 8, Bgh + gBo + 8);
        cp16(b0p + 3 * STG + sOff,     Bgl + gBo);
        cp16(b0p + 3 * STG + sOff + 8, Bgl + gBo + 8);
        asm volatile("cp.async.commit_group;\n");
    }

    const int nt = K >> 5;
    for (int t = 0; t < nt; t++) {
        if (t + 1 < nt) {
            __nv_bfloat16* bp = sm + ((t + 1) & 1) * 4 * STG;
            const size_t k0 = (size_t)(t + 1) * 32;
            cp16(bp + sOff,               Agh + gAo + k0);
            cp16(bp + sOff + 8,           Agh + gAo + k0 + 8);
            cp16(bp + STG + sOff,         Agl + gAo + k0);
            cp16(bp + STG + sOff + 8,     Agl + gAo + k0 + 8);
            cp16(bp + 2 * STG + sOff,     Bgh + gBo + k0);
            cp16(bp + 2 * STG + sOff + 8, Bgh + gBo + k0 + 8);
            cp16(bp + 3 * STG + sOff,     Bgl + gBo + k0);
            cp16(bp + 3 * STG + sOff + 8, Bgl + gBo + k0 + 8);
            asm volatile("cp.async.commit_group;\n");
            asm volatile("cp.async.wait_group 1;\n" ::: "memory");
        } else {
            asm volatile("cp.async.wait_group 0;\n" ::: "memory");
        }
        __syncthreads();

        __nv_bfloat16* base = sm + (t & 1) * 4 * STG;
        __nv_bfloat16* sAh = base;
        __nv_bfloat16* sAl = base + STG;
        __nv_bfloat16* sBh = base + 2 * STG;
        __nv_bfloat16* sBl = base + 3 * STG;

        #pragma unroll
        for (int kk = 0; kk < 32; kk += 16) {
            unsigned ah[2][4], al[2][4], bb[4][4];
            #pragma unroll
            for (int mt = 0; mt < 2; mt++)
                ldsm4(ah[mt][0], ah[mt][1], ah[mt][2], ah[mt][3],
                      sAh + aoff[mt] + kk);
            #pragma unroll
            for (int mt = 0; mt < 2; mt++)
                ldsm4(al[mt][0], al[mt][1], al[mt][2], al[mt][3],
                      sAl + aoff[mt] + kk);
            #pragma unroll
            for (int gn = 0; gn < 4; gn++)
                ldsm4(bb[gn][0], bb[gn][1], bb[gn][2], bb[gn][3],
                      sBh + boff[gn] + kk);
            // Ah*Bh + Al*Bh
            #pragma unroll
            for (int mt = 0; mt < 2; mt++)
                #pragma unroll
                for (int gn = 0; gn < 4; gn++) {
                    mma16816(acc[mt][2 * gn],     ah[mt], bb[gn][0], bb[gn][1]);
                    mma16816(acc[mt][2 * gn + 1], ah[mt], bb[gn][2], bb[gn][3]);
                    mma16816(acc[mt][2 * gn],     al[mt], bb[gn][0], bb[gn][1]);
                    mma16816(acc[mt][2 * gn + 1], al[mt], bb[gn][2], bb[gn][3]);
                }
            // Ah*Bl
            #pragma unroll
            for (int gn = 0; gn < 4; gn++)
                ldsm4(bb[gn][0], bb[gn][1], bb[gn][2], bb[gn][3],
                      sBl + boff[gn] + kk);
            #pragma unroll
            for (int mt = 0; mt < 2; mt++)
                #pragma unroll
                for (int gn = 0; gn < 4; gn++) {
                    mma16816(acc[mt][2 * gn],     ah[mt], bb[gn][0], bb[gn][1]);
                    mma16816(acc[mt][2 * gn + 1], ah[mt], bb[gn][2], bb[gn][3]);
                }
        }
        __syncthreads();
    }

    // epilogue
    const int cr = lane >> 2;
    const int cc = (lane & 3) * 2;
    #pragma unroll
    for (int mt = 0; mt < 2; mt++) {
        const int grow = m0 + m0w + mt * 16 + cr;
        #pragma unroll
        for (int nt8 = 0; nt8 < 8; nt8++) {
            const int gcol = n0 + n0w + nt8 * 8 + cc;
            const float b0 = bias[gcol], b1 = bias[gcol + 1];
            float2 v0 = {acc[mt][nt8][0] + b0, acc[mt][nt8][1] + b1};
            float2 v1 = {acc[mt][nt8][2] + b0, acc[mt][nt8][3] + b1};
            *(float2*)&C[(size_t)grow * N + gcol]       = v0;
            *(float2*)&C[(size_t)(grow + 8) * N + gcol] = v1;
        }
    }
}

// ======================================================================
// RoPE (YaRN), in place on g_Q and g_K.
// ======================================================================
__global__ __launch_bounds__(256)
void rope_kernel(const int* __restrict__ pos_ids)
{
    const int gid = blockIdx.x * blockDim.x + threadIdx.x;
    const int i   = gid & 31;
    const int rh  = gid >> 5;
    const int hr  = rh % (NH_ + NKV_);
    const int row = rh / (NH_ + NKV_);

    const int p = pos_ids[row];

    float* ptr;
    if (hr < NH_) ptr = g_Q + ((size_t)row * NH_ + hr) * HD_;
    else          ptr = g_K + ((size_t)row * NKV_ + (hr - NH_)) * HD_;

    const float expo = (float)(2 * i) * (1.0f / 64.0f);
    const float freq = 1.0f / powf(10000.0f, expo);
    const float wl   = 6.2831853071795864769f / freq;
    float tt = (wl - 32.0f) / 992.0f;
    tt = fminf(fmaxf(tt, 0.0f), 1.0f);
    const float eff  = freq * (1.0f - tt) + (freq * 0.25f) * tt;
    const float ang  = ((float)p * eff) * 1.1386294361119891f;

    float sv, cv;
    sincosf(ang, &sv, &cv);

    const float x1 = ptr[i];
    const float x2 = ptr[i + 32];
    ptr[i]      = x1 * cv - x2 * sv;
    ptr[i + 32] = x2 * cv + x1 * sv;
}

// ======================================================================
// Sliding-window GQA attention with sink (unchanged from passing R4).
// ======================================================================
#define KWIN 255
#define PITCH 65
#define ATT_SMEM ((2 * KWIN * PITCH + 8 * 64) * (int)sizeof(float))

__global__ __launch_bounds__(256, 1)
void attn_kernel(const float* __restrict__ sinks)
{
    extern __shared__ float smf[];
    float* Ks = smf;
    float* Vs = smf + KWIN * PITCH;
    float* Qw = Vs + KWIN * PITCH;

    const int tid  = threadIdx.x;
    const int w    = tid >> 5;
    const int lane = tid & 31;
    const int qt   = blockIdx.x;
    const int kvh  = blockIdx.y;
    const int b    = blockIdx.z;
    const int q0   = qt * 128;

    for (int idx = tid; idx < KWIN * HD_; idx += 256) {
        const int kt = idx >> 6;
        const int d  = idx & 63;
        const int t  = q0 - 127 + kt;
        float kv = 0.0f, vv = 0.0f;
        if (t >= 0) {
            const size_t base = ((size_t)(b * S_ + t) * NKV_ + kvh) * HD_ + d;
            kv = g_K[base];
            vv = g_V[base];
        }
        Ks[kt * PITCH + d] = kv;
        Vs[kt * PITCH + d] = vv;
    }
    __syncthreads();

    for (int g = 0; g < GS_; g++) {
        const int h = kvh * GS_ + g;
        const float sinkv = sinks[h];

        for (int r = w; r < 128; r += 8) {
            const int s = q0 + r;
            const float* Qrow = g_Q + ((size_t)(b * S_ + s) * NH_ + h) * HD_;
            __syncwarp();
            Qw[w * 64 + lane]      = Qrow[lane];
            Qw[w * 64 + lane + 32] = Qrow[lane + 32];
            __syncwarp();

            float sc0 = 0.f, sc1 = 0.f, sc2 = 0.f, sc3 = 0.f;
            const float* kp = Ks + (r + lane) * PITCH;
            const float* qp = Qw + w * 64;
            #pragma unroll 8
            for (int d = 0; d < 64; d++) {
                const float qd = qp[d];
                sc0 += qd * kp[d];
                sc1 += qd * kp[32 * PITCH + d];
                sc2 += qd * kp[64 * PITCH + d];
                sc3 += qd * kp[96 * PITCH + d];
            }
            const float NEG = -1e30f;
            const int tb = q0 - 127 + r + lane;
            sc0 = (tb      >= 0) ? sc0 * 0.125f : NEG;
            sc1 = (tb + 32 >= 0) ? sc1 * 0.125f : NEG;
            sc2 = (tb + 64 >= 0) ? sc2 * 0.125f : NEG;
            sc3 = (tb + 96 >= 0) ? sc3 * 0.125f : NEG;

            float m = fmaxf(fmaxf(sc0, sc1), fmaxf(sc2, sc3));
            #pragma unroll
            for (int o = 16; o; o >>= 1)
                m = fmaxf(m, __shfl_xor_sync(0xffffffffu, m, o));
            m = fmaxf(m, sinkv);

            const float e0 = __expf(sc0 - m), e1 = __expf(sc1 - m);
            const float e2 = __expf(sc2 - m), e3 = __expf(sc3 - m);
            float sum = e0 + e1 + e2 + e3;
            #pragma unroll
            for (int o = 16; o; o >>= 1)
                sum += __shfl_xor_sync(0xffffffffu, sum, o);
            sum += __expf(sinkv - m);
            const float inv = 1.0f / sum;
            float p[4] = {e0 * inv, e1 * inv, e2 * inv, e3 * inv};

            float o0 = 0.f, o1 = 0.f;
            #pragma unroll
            for (int c = 0; c < 4; c++) {
                const float* vp = Vs + (r + c * 32) * PITCH;
                #pragma unroll 8
                for (int l2 = 0; l2 < 32; l2++) {
                    const float pt = __shfl_sync(0xffffffffu, p[c], l2);
                    o0 += pt * vp[l2 * PITCH + lane];
                    o1 += pt * vp[l2 * PITCH + lane + 32];
                }
            }
            float* orow = g_ctx + (size_t)(b * S_ + s) * (NH_ * HD_) + h * HD_;
            orow[lane]      = o0;
            orow[lane + 32] = o1;
        }
    }
}

// ======================================================================
// Launch
// ======================================================================
#define GEMM_SMEM (2 * 4 * STG * (int)sizeof(__nv_bfloat16))  // 81920

extern "C" void kernel_launch(void* const* d_in, const int* in_sizes, int n_in,
                              void* d_out, int out_size)
{
    const float* x     = (const float*)d_in[0];
    const float* Wq    = (const float*)d_in[1];
    const float* bq    = (const float*)d_in[2];
    const float* Wk    = (const float*)d_in[3];
    const float* bk    = (const float*)d_in[4];
    const float* Wv    = (const float*)d_in[5];
    const float* bv    = (const float*)d_in[6];
    const float* Wo    = (const float*)d_in[7];
    const float* bo    = (const float*)d_in[8];
    const float* sinks = (const float*)d_in[9];
    const int*   pos   = (const int*)d_in[10];
    float* out = (float*)d_out;

    cudaFuncSetAttribute(attn_kernel,
                         cudaFuncAttributeMaxDynamicSharedMemorySize, ATT_SMEM);
    cudaFuncSetAttribute(gemm_bf16,
                         cudaFuncAttributeMaxDynamicSharedMemorySize, GEMM_SMEM);

    // hi/lo conversions
    convert_kernel<<<(MROWS * EMB_) / 1024, 256>>>(x, 0, 0);
    convert_kernel<<<(NH_ * HD_ * EMB_) / 1024, 256>>>(Wq, 0, 1);
    convert_kernel<<<(NKV_ * HD_ * EMB_) / 1024, 256>>>(Wk, 0, 2);
    convert_kernel<<<(NKV_ * HD_ * EMB_) / 1024, 256>>>(Wv, 0, 3);
    convert_kernel<<<(EMB_ * NH_ * HD_) / 1024, 256>>>(Wo, 0, 4);

    // QKV projections (tensor core)
    gemm_bf16<<<dim3(NH_ * HD_ / 128,  MROWS / 128), 256, GEMM_SMEM>>>(
        0, 0, 1, bq, nullptr, MROWS, NH_ * HD_, EMB_);
    gemm_bf16<<<dim3(NKV_ * HD_ / 128, MROWS / 128), 256, GEMM_SMEM>>>(
        0, 1, 2, bk, nullptr, MROWS, NKV_ * HD_, EMB_);
    gemm_bf16<<<dim3(NKV_ * HD_ / 128, MROWS / 128), 256, GEMM_SMEM>>>(
        0, 2, 3, bv, nullptr, MROWS, NKV_ * HD_, EMB_);

    // RoPE
    rope_kernel<<<(MROWS * (NH_ + NKV_) * 32) / 256, 256>>>(pos);

    // Attention -> g_ctx
    attn_kernel<<<dim3(S_ / 128, NKV_, B_), 256, ATT_SMEM>>>(sinks);

    // ctx -> hi/lo, then output projection
    convert_kernel<<<(MROWS * EMB_) / 1024, 256>>>(nullptr, 1, 5);
    gemm_bf16<<<dim3(EMB_ / 128, MROWS / 128), 256, GEMM_SMEM>>>(
        1, 3, 0, bo, out, MROWS, EMB_, EMB_);
}